// round 4
// baseline (speedup 1.0000x reference)
#include <cuda_runtime.h>
#include <math.h>

// Problem constants
#define BDIM 4
#define SDIM 4096
#define DDIM 1024

// Scratch (device globals — allocation-free per harness rules)
__device__ float g_qkv[(size_t)BDIM * SDIM * 3 * DDIM];   // [B*S, 3D] row-major
__device__ float g_kt [(size_t)BDIM * DDIM * SDIM];       // [B][D][S]  (K transposed)
__device__ float g_sc [(size_t)BDIM * SDIM * SDIM];       // [B][S][S]  scores / attn

// ---------------------------------------------------------------------------
// Packed fp32x2 FMA (sm_103a). Exact fp32 per lane; 2x fma-pipe throughput.
// ---------------------------------------------------------------------------
__device__ __forceinline__ float2 ffma2(float a, float2 b, float2 c) {
    float2 r;
    asm("{\n\t"
        ".reg .b64 ua, ub, uc;\n\t"
        "mov.b64 ua, {%2, %2};\n\t"
        "mov.b64 ub, {%3, %4};\n\t"
        "mov.b64 uc, {%5, %6};\n\t"
        "fma.rn.f32x2 uc, ua, ub, uc;\n\t"
        "mov.b64 {%0, %1}, uc;\n\t"
        "}"
        : "=f"(r.x), "=f"(r.y)
        : "f"(a), "f"(b.x), "f"(b.y), "f"(c.x), "f"(c.y));
    return r;
}

// ---------------------------------------------------------------------------
// NN SGEMM: C[M,N] = A[M,K] @ B[K,N] (+ bias[N]), batched via blockIdx.z.
// Tile 128x128x16, 256 threads, 8x8 per thread. M,N % 128 == 0, K % 16 == 0.
// Register double-buffered global loads + double-buffered SMEM.
// ---------------------------------------------------------------------------
__global__ __launch_bounds__(256, 1)
void gemm_f32(const float* __restrict__ A, int lda, long long sA,
              const float* __restrict__ B, int ldb, long long sB,
              float* __restrict__ C, int ldc, long long sC,
              int K, const float* __restrict__ bias)
{
    __shared__ float As[2][16][132];   // A tile transposed [k][m], padded
    __shared__ float Bs[2][16][128];   // B tile [k][n]

    const int bx = blockIdx.x, by = blockIdx.y, bz = blockIdx.z;
    A += (long long)bz * sA + (long long)by * 128 * lda;
    B += (long long)bz * sB + bx * 128;
    C += (long long)bz * sC + (long long)by * 128 * ldc + bx * 128;

    const int tid = threadIdx.x;
    const int tx  = tid & 15;          // 0..15  -> n micro-tile
    const int ty  = tid >> 4;          // 0..15  -> m micro-tile
    const int arow = tid >> 2;         // 0..63  (and +64)
    const int ac4  = (tid & 3) << 2;   // k offset within tile (0,4,8,12)
    const int brow = tid >> 5;         // 0..7   (and +8)
    const int bc4  = (tid & 31) << 2;  // n offset (0..124)

    float2 acc[8][4];
    #pragma unroll
    for (int i = 0; i < 8; i++)
        #pragma unroll
        for (int j = 0; j < 4; j++)
            acc[i][j] = make_float2(0.f, 0.f);

    // Prologue: load tile 0
    float4 a0 = *(const float4*)(A + (long long)arow        * lda + ac4);
    float4 a1 = *(const float4*)(A + (long long)(arow + 64) * lda + ac4);
    float4 b0 = *(const float4*)(B + (long long)brow        * ldb + bc4);
    float4 b1 = *(const float4*)(B + (long long)(brow + 8)  * ldb + bc4);

    As[0][ac4 + 0][arow]      = a0.x; As[0][ac4 + 1][arow]      = a0.y;
    As[0][ac4 + 2][arow]      = a0.z; As[0][ac4 + 3][arow]      = a0.w;
    As[0][ac4 + 0][arow + 64] = a1.x; As[0][ac4 + 1][arow + 64] = a1.y;
    As[0][ac4 + 2][arow + 64] = a1.z; As[0][ac4 + 3][arow + 64] = a1.w;
    *(float4*)&Bs[0][brow][bc4]     = b0;
    *(float4*)&Bs[0][brow + 8][bc4] = b1;
    __syncthreads();

    const int nk = K >> 4;
    for (int t = 0; t < nk; ++t) {
        const int cur = t & 1;
        if (t + 1 < nk) {   // prefetch next tile into registers
            const float* Ap = A + (t + 1) * 16;
            const float* Bp = B + (long long)(t + 1) * 16 * ldb;
            a0 = *(const float4*)(Ap + (long long)arow        * lda + ac4);
            a1 = *(const float4*)(Ap + (long long)(arow + 64) * lda + ac4);
            b0 = *(const float4*)(Bp + (long long)brow        * ldb + bc4);
            b1 = *(const float4*)(Bp + (long long)(brow + 8)  * ldb + bc4);
        }

        #pragma unroll
        for (int kk = 0; kk < 16; ++kk) {
            float4 af0 = *(const float4*)&As[cur][kk][ty * 8];
            float4 af1 = *(const float4*)&As[cur][kk][ty * 8 + 4];
            float4 bf0 = *(const float4*)&Bs[cur][kk][tx * 8];
            float4 bf1 = *(const float4*)&Bs[cur][kk][tx * 8 + 4];
            float  am[8] = {af0.x, af0.y, af0.z, af0.w, af1.x, af1.y, af1.z, af1.w};
            float2 bp[4] = {make_float2(bf0.x, bf0.y), make_float2(bf0.z, bf0.w),
                            make_float2(bf1.x, bf1.y), make_float2(bf1.z, bf1.w)};
            #pragma unroll
            for (int i = 0; i < 8; i++)
                #pragma unroll
                for (int j = 0; j < 4; j++)
                    acc[i][j] = ffma2(am[i], bp[j], acc[i][j]);
        }

        if (t + 1 < nk) {   // stage next tile into the other smem buffer
            const int nx = cur ^ 1;
            As[nx][ac4 + 0][arow]      = a0.x; As[nx][ac4 + 1][arow]      = a0.y;
            As[nx][ac4 + 2][arow]      = a0.z; As[nx][ac4 + 3][arow]      = a0.w;
            As[nx][ac4 + 0][arow + 64] = a1.x; As[nx][ac4 + 1][arow + 64] = a1.y;
            As[nx][ac4 + 2][arow + 64] = a1.z; As[nx][ac4 + 3][arow + 64] = a1.w;
            *(float4*)&Bs[nx][brow][bc4]     = b0;
            *(float4*)&Bs[nx][brow + 8][bc4] = b1;
        }
        __syncthreads();
    }

    float badd[8];
    #pragma unroll
    for (int j = 0; j < 8; j++)
        badd[j] = bias ? bias[bx * 128 + tx * 8 + j] : 0.0f;

    #pragma unroll
    for (int i = 0; i < 8; i++) {
        float* cp = C + (long long)(ty * 8 + i) * ldc + tx * 8;
        float4 o0 = make_float4(acc[i][0].x + badd[0], acc[i][0].y + badd[1],
                                acc[i][1].x + badd[2], acc[i][1].y + badd[3]);
        float4 o1 = make_float4(acc[i][2].x + badd[4], acc[i][2].y + badd[5],
                                acc[i][3].x + badd[6], acc[i][3].y + badd[7]);
        *(float4*)cp       = o0;
        *(float4*)(cp + 4) = o1;
    }
}

// ---------------------------------------------------------------------------
// Transpose K section of qkv into [B][D][S] so scores GEMM is NN.
// ---------------------------------------------------------------------------
__global__ void transposeK_kernel(const float* __restrict__ qkv, float* __restrict__ kt)
{
    __shared__ float tile[32][33];
    const int b  = blockIdx.z;
    const int s0 = blockIdx.x << 5;
    const int d0 = blockIdx.y << 5;
    const int x = threadIdx.x, y = threadIdx.y;   // 32 x 8
    #pragma unroll
    for (int j = 0; j < 32; j += 8)
        tile[y + j][x] =
            qkv[((long long)(b * SDIM + s0 + y + j)) * (3 * DDIM) + DDIM + d0 + x];
    __syncthreads();
    #pragma unroll
    for (int j = 0; j < 32; j += 8)
        kt[((long long)b * DDIM + d0 + y + j) * SDIM + s0 + x] = tile[x][y + j];
}

// ---------------------------------------------------------------------------
// Row softmax over 4096 columns, scale applied before max-subtraction.
// One 256-thread block per row; row stays in registers (16 floats/thread).
// ---------------------------------------------------------------------------
__device__ __forceinline__ float warpMax(float v) {
    #pragma unroll
    for (int o = 16; o > 0; o >>= 1) v = fmaxf(v, __shfl_xor_sync(0xffffffffu, v, o));
    return v;
}
__device__ __forceinline__ float warpSum(float v) {
    #pragma unroll
    for (int o = 16; o > 0; o >>= 1) v += __shfl_xor_sync(0xffffffffu, v, o);
    return v;
}

__global__ __launch_bounds__(256, 4)
void softmax4096(float* __restrict__ s, float scale)
{
    float* p = s + (long long)blockIdx.x * 4096;
    const int t = threadIdx.x;
    const int lane = t & 31, wid = t >> 5;
    __shared__ float red[8];

    float4 v[4];
    #pragma unroll
    for (int i = 0; i < 4; i++) {
        v[i] = *(const float4*)(p + i * 1024 + t * 4);
        v[i].x *= scale; v[i].y *= scale; v[i].z *= scale; v[i].w *= scale;
    }

    float m = v[0].x;
    #pragma unroll
    for (int i = 0; i < 4; i++) {
        m = fmaxf(m, v[i].x); m = fmaxf(m, v[i].y);
        m = fmaxf(m, v[i].z); m = fmaxf(m, v[i].w);
    }
    m = warpMax(m);
    if (lane == 0) red[wid] = m;
    __syncthreads();
    m = red[0];
    #pragma unroll
    for (int j = 1; j < 8; j++) m = fmaxf(m, red[j]);

    float sum = 0.f;
    #pragma unroll
    for (int i = 0; i < 4; i++) {
        v[i].x = expf(v[i].x - m); v[i].y = expf(v[i].y - m);
        v[i].z = expf(v[i].z - m); v[i].w = expf(v[i].w - m);
        sum += v[i].x + v[i].y + v[i].z + v[i].w;
    }
    sum = warpSum(sum);
    __syncthreads();              // red reuse
    if (lane == 0) red[wid] = sum;
    __syncthreads();
    float tot = red[0];
    #pragma unroll
    for (int j = 1; j < 8; j++) tot += red[j];
    const float inv = 1.0f / tot;

    #pragma unroll
    for (int i = 0; i < 4; i++) {
        v[i].x *= inv; v[i].y *= inv; v[i].z *= inv; v[i].w *= inv;
        *(float4*)(p + i * 1024 + t * 4) = v[i];
    }
}

// ---------------------------------------------------------------------------
// Launch
// ---------------------------------------------------------------------------
extern "C" void kernel_launch(void* const* d_in, const int* in_sizes, int n_in,
                              void* d_out, int out_size)
{
    (void)in_sizes; (void)n_in; (void)out_size;
    const float* x = (const float*)d_in[0];   // [B,S,D]
    const float* W = (const float*)d_in[1];   // [D,3D]
    const float* b = (const float*)d_in[2];   // [3D]
    float* out = (float*)d_out;               // [B,S,D]

    float *qkv, *kt, *sc;
    cudaGetSymbolAddress((void**)&qkv, g_qkv);
    cudaGetSymbolAddress((void**)&kt,  g_kt);
    cudaGetSymbolAddress((void**)&sc,  g_sc);

    // 1) qkv = x @ W + b   (M=16384, N=3072, K=1024)
    gemm_f32<<<dim3(3 * DDIM / 128, BDIM * SDIM / 128, 1), 256>>>(
        x,   DDIM,     0LL,
        W,   3 * DDIM, 0LL,
        qkv, 3 * DDIM, 0LL,
        DDIM, b);

    // 2) Kt[b][d][s] = K[b][s][d]
    transposeK_kernel<<<dim3(SDIM / 32, DDIM / 32, BDIM), dim3(32, 8)>>>(qkv, kt);

    // 3) scores = Q @ Kt   (per batch: M=4096, N=4096, K=1024)
    gemm_f32<<<dim3(SDIM / 128, SDIM / 128, BDIM), 256>>>(
        qkv, 3 * DDIM, (long long)SDIM * 3 * DDIM,
        kt,  SDIM,     (long long)DDIM * SDIM,
        sc,  SDIM,     (long long)SDIM * SDIM,
        DDIM, nullptr);

    // 4) softmax rows (scale = D^-0.5 = 1/32)
    softmax4096<<<BDIM * SDIM, 256>>>(sc, 0.03125f);

    // 5) out = P @ V       (per batch: M=4096, N=1024, K=4096)
    gemm_f32<<<dim3(DDIM / 128, SDIM / 128, BDIM), 256>>>(
        sc,             SDIM,     (long long)SDIM * SDIM,
        qkv + 2 * DDIM, 3 * DDIM, (long long)SDIM * 3 * DDIM,
        out,            DDIM,     (long long)SDIM * DDIM,
        SDIM, nullptr);
}

// round 8
// speedup vs baseline: 2.3437x; 2.3437x over previous
#include <cuda_runtime.h>
#include <stdint.h>
#include <math.h>

#define BDIM 4
#define SDIM 4096
#define DDIM 1024

// Scratch (device globals — allocation-free per harness rules)
__device__ float g_qkv[(size_t)BDIM * SDIM * 3 * DDIM];  // [B*S, 3D]
__device__ float g_wt [(size_t)3 * DDIM * DDIM];         // W^T  [3D, D]
__device__ float g_vt [(size_t)BDIM * DDIM * SDIM];      // V^T  [B][D][S]
__device__ float g_sc [(size_t)BDIM * SDIM * SDIM];      // scores / attn [B][S][S]

// ---------------------------------------------------------------------------
// tf32 helpers (arch-portable PTX only — NO tcgen05; harness targets sm_103 base)
// ---------------------------------------------------------------------------
__device__ __forceinline__ uint32_t f2tf32(float f) {
    uint32_t r; asm("cvt.rna.tf32.f32 %0, %1;" : "=r"(r) : "f"(f)); return r;
}

__device__ __forceinline__ void mma16n8k8(float c[4],
                                          uint32_t a0, uint32_t a1, uint32_t a2, uint32_t a3,
                                          uint32_t b0, uint32_t b1) {
    asm volatile(
        "mma.sync.aligned.m16n8k8.row.col.f32.tf32.tf32.f32 "
        "{%0,%1,%2,%3}, {%4,%5,%6,%7}, {%8,%9}, {%0,%1,%2,%3};"
        : "+f"(c[0]), "+f"(c[1]), "+f"(c[2]), "+f"(c[3])
        : "r"(a0), "r"(a1), "r"(a2), "r"(a3), "r"(b0), "r"(b1));
}

// ---------------------------------------------------------------------------
// TN tf32 GEMM via mma.sync: C[M,N] = A[M,K] @ B[N,K]^T (+ bias[N]). Batched z.
// CTA 128x128x32, 256 threads (8 warps = 2M x 4N, warp tile 64x32).
// gmem->reg prefetch, cvt.rna at staging, double-buffered padded SMEM.
// Row pad = 36 floats: fragment bank = (4*group + t) -> conflict-free.
// ---------------------------------------------------------------------------
#define TM 128
#define TN 128
#define TK 32
#define ROWP 36                               // padded row length (floats)
#define TILE_U (128 * ROWP)                   // one tile in uint32s (4608)
#define SMEM_BYTES (4 * TILE_U * 4)           // A0 A1 B0 B1 = 73728 B

extern __shared__ uint32_t smu[];

__global__ __launch_bounds__(256, 1)
void gemm_tf32mma(const float* __restrict__ A, int lda, long long sA,
                  const float* __restrict__ B, int ldb, long long sB,
                  float* __restrict__ C, int ldc, long long sC,
                  int K, const float* __restrict__ bias)
{
    const int tid = threadIdx.x;
    const int wid = tid >> 5, lid = tid & 31;
    const int g = lid >> 2, tq = lid & 3;      // mma group / quad
    const int wm = wid & 1, wn = wid >> 1;     // warp position: 2(M) x 4(N)
    const int bx = blockIdx.x, by = blockIdx.y, bz = blockIdx.z;

    A += (long long)bz * sA + (long long)(by * TM) * lda;
    B += (long long)bz * sB + (long long)(bx * TN) * ldb;
    C += (long long)bz * sC + (long long)(by * TM) * ldc + bx * TN;

    uint32_t* As0 = smu;
    uint32_t* Bs0 = smu + 2 * TILE_U;

    // Staging map: 2 threads per row, 16 floats each (4 x float4)
    const int srow = tid >> 1;
    const int sk   = (tid & 1) * 16;
    const float* Ap = A + (long long)srow * lda + sk;
    const float* Bp = B + (long long)srow * ldb + sk;
    const int soff = srow * ROWP + sk;

    float acc[4][4][4];
    #pragma unroll
    for (int i = 0; i < 4; i++)
        #pragma unroll
        for (int j = 0; j < 4; j++)
            #pragma unroll
            for (int r = 0; r < 4; r++) acc[i][j][r] = 0.f;

    // ---- stage tile 0 into buffer 0 ----
    {
        #pragma unroll
        for (int i = 0; i < 4; i++) {
            float4 va = *(const float4*)(Ap + i * 4);
            float4 vb = *(const float4*)(Bp + i * 4);
            As0[soff + i * 4 + 0] = f2tf32(va.x); As0[soff + i * 4 + 1] = f2tf32(va.y);
            As0[soff + i * 4 + 2] = f2tf32(va.z); As0[soff + i * 4 + 3] = f2tf32(va.w);
            Bs0[soff + i * 4 + 0] = f2tf32(vb.x); Bs0[soff + i * 4 + 1] = f2tf32(vb.y);
            Bs0[soff + i * 4 + 2] = f2tf32(vb.z); Bs0[soff + i * 4 + 3] = f2tf32(vb.w);
        }
    }
    __syncthreads();

    const int NK = K / TK;
    const int aRow0 = wm * 64 + g;             // + mb*16 (+8)
    const int bRow0 = wn * 32 + g;             // + nb*8

    for (int t = 0; t < NK; ++t) {
        const int cur = t & 1;
        const uint32_t* Ac = As0 + cur * TILE_U;
        const uint32_t* Bc = Bs0 + cur * TILE_U;

        // prefetch next tile (overlaps with MMA below)
        const bool more = (t + 1 < NK);
        float4 pa[4], pb[4];
        if (more) {
            const float* An = Ap + (t + 1) * TK;
            const float* Bn = Bp + (t + 1) * TK;
            #pragma unroll
            for (int i = 0; i < 4; i++) {
                pa[i] = *(const float4*)(An + i * 4);
                pb[i] = *(const float4*)(Bn + i * 4);
            }
        }

        // ---- compute: 4 k-steps of k=8 ----
        #pragma unroll
        for (int ks = 0; ks < 4; ++ks) {
            const int c0 = ks * 8 + tq;
            uint32_t af[4][4], bf[4][2];
            #pragma unroll
            for (int mb = 0; mb < 4; mb++) {
                const int r = (aRow0 + mb * 16) * ROWP;
                af[mb][0] = Ac[r + c0];
                af[mb][1] = Ac[r + 8 * ROWP + c0];
                af[mb][2] = Ac[r + c0 + 4];
                af[mb][3] = Ac[r + 8 * ROWP + c0 + 4];
            }
            #pragma unroll
            for (int nb = 0; nb < 4; nb++) {
                const int r = (bRow0 + nb * 8) * ROWP;
                bf[nb][0] = Bc[r + c0];
                bf[nb][1] = Bc[r + c0 + 4];
            }
            #pragma unroll
            for (int mb = 0; mb < 4; mb++)
                #pragma unroll
                for (int nb = 0; nb < 4; nb++)
                    mma16n8k8(acc[mb][nb], af[mb][0], af[mb][1], af[mb][2], af[mb][3],
                              bf[nb][0], bf[nb][1]);
        }

        // ---- stage next tile into the other buffer ----
        if (more) {
            uint32_t* An = As0 + (cur ^ 1) * TILE_U;
            uint32_t* Bn = Bs0 + (cur ^ 1) * TILE_U;
            #pragma unroll
            for (int i = 0; i < 4; i++) {
                An[soff + i * 4 + 0] = f2tf32(pa[i].x); An[soff + i * 4 + 1] = f2tf32(pa[i].y);
                An[soff + i * 4 + 2] = f2tf32(pa[i].z); An[soff + i * 4 + 3] = f2tf32(pa[i].w);
                Bn[soff + i * 4 + 0] = f2tf32(pb[i].x); Bn[soff + i * 4 + 1] = f2tf32(pb[i].y);
                Bn[soff + i * 4 + 2] = f2tf32(pb[i].z); Bn[soff + i * 4 + 3] = f2tf32(pb[i].w);
            }
        }
        __syncthreads();
    }

    // ---- epilogue ----
    float badd[4][2];
    #pragma unroll
    for (int nb = 0; nb < 4; nb++) {
        const int col = wn * 32 + nb * 8 + tq * 2;
        badd[nb][0] = bias ? __ldg(bias + bx * TN + col)     : 0.f;
        badd[nb][1] = bias ? __ldg(bias + bx * TN + col + 1) : 0.f;
    }
    #pragma unroll
    for (int mb = 0; mb < 4; mb++) {
        const int row = wm * 64 + mb * 16 + g;
        #pragma unroll
        for (int nb = 0; nb < 4; nb++) {
            const int col = wn * 32 + nb * 8 + tq * 2;
            float2 v0 = make_float2(acc[mb][nb][0] + badd[nb][0],
                                    acc[mb][nb][1] + badd[nb][1]);
            float2 v1 = make_float2(acc[mb][nb][2] + badd[nb][0],
                                    acc[mb][nb][3] + badd[nb][1]);
            *(float2*)(C + (long long)row * ldc + col)       = v0;
            *(float2*)(C + (long long)(row + 8) * ldc + col) = v1;
        }
    }
}

// ---------------------------------------------------------------------------
// Generic 32x32 tiled transpose: out[c][r] = in[r][c], batched.
// ---------------------------------------------------------------------------
__global__ void transpose_f32(const float* __restrict__ in, long long sIn, int ldin,
                              float* __restrict__ out, long long sOut, int ldout)
{
    __shared__ float tile[32][33];
    const int b  = blockIdx.z;
    const int c0 = blockIdx.x << 5;
    const int r0 = blockIdx.y << 5;
    const int x = threadIdx.x, y = threadIdx.y;     // 32 x 8
    const float* ip = in + (long long)b * sIn;
    float* op = out + (long long)b * sOut;
    #pragma unroll
    for (int j = 0; j < 32; j += 8)
        tile[y + j][x] = ip[(long long)(r0 + y + j) * ldin + c0 + x];
    __syncthreads();
    #pragma unroll
    for (int j = 0; j < 32; j += 8)
        op[(long long)(c0 + y + j) * ldout + r0 + x] = tile[x][y + j];
}

// ---------------------------------------------------------------------------
// Row softmax over 4096 columns (scale folded in). Already at DRAM roofline.
// ---------------------------------------------------------------------------
__device__ __forceinline__ float warpMax(float v) {
    #pragma unroll
    for (int o = 16; o > 0; o >>= 1) v = fmaxf(v, __shfl_xor_sync(0xffffffffu, v, o));
    return v;
}
__device__ __forceinline__ float warpSum(float v) {
    #pragma unroll
    for (int o = 16; o > 0; o >>= 1) v += __shfl_xor_sync(0xffffffffu, v, o);
    return v;
}

__global__ __launch_bounds__(256, 4)
void softmax4096(float* __restrict__ s, float scale)
{
    float* p = s + (long long)blockIdx.x * 4096;
    const int t = threadIdx.x;
    const int lane = t & 31, wid = t >> 5;
    __shared__ float red[8];

    float4 v[4];
    #pragma unroll
    for (int i = 0; i < 4; i++) {
        v[i] = *(const float4*)(p + i * 1024 + t * 4);
        v[i].x *= scale; v[i].y *= scale; v[i].z *= scale; v[i].w *= scale;
    }
    float m = v[0].x;
    #pragma unroll
    for (int i = 0; i < 4; i++) {
        m = fmaxf(m, v[i].x); m = fmaxf(m, v[i].y);
        m = fmaxf(m, v[i].z); m = fmaxf(m, v[i].w);
    }
    m = warpMax(m);
    if (lane == 0) red[wid] = m;
    __syncthreads();
    m = red[0];
    #pragma unroll
    for (int j = 1; j < 8; j++) m = fmaxf(m, red[j]);

    float sum = 0.f;
    #pragma unroll
    for (int i = 0; i < 4; i++) {
        v[i].x = expf(v[i].x - m); v[i].y = expf(v[i].y - m);
        v[i].z = expf(v[i].z - m); v[i].w = expf(v[i].w - m);
        sum += v[i].x + v[i].y + v[i].z + v[i].w;
    }
    sum = warpSum(sum);
    __syncthreads();
    if (lane == 0) red[wid] = sum;
    __syncthreads();
    float tot = red[0];
    #pragma unroll
    for (int j = 1; j < 8; j++) tot += red[j];
    const float inv = 1.0f / tot;

    #pragma unroll
    for (int i = 0; i < 4; i++) {
        v[i].x *= inv; v[i].y *= inv; v[i].z *= inv; v[i].w *= inv;
        *(float4*)(p + i * 1024 + t * 4) = v[i];
    }
}

// ---------------------------------------------------------------------------
// Launch
// ---------------------------------------------------------------------------
extern "C" void kernel_launch(void* const* d_in, const int* in_sizes, int n_in,
                              void* d_out, int out_size)
{
    (void)in_sizes; (void)n_in; (void)out_size;
    const float* x = (const float*)d_in[0];   // [B,S,D]
    const float* W = (const float*)d_in[1];   // [D,3D]
    const float* b = (const float*)d_in[2];   // [3D]
    float* out = (float*)d_out;               // [B,S,D]

    float *qkv, *wt, *vt, *sc;
    cudaGetSymbolAddress((void**)&qkv, g_qkv);
    cudaGetSymbolAddress((void**)&wt,  g_wt);
    cudaGetSymbolAddress((void**)&vt,  g_vt);
    cudaGetSymbolAddress((void**)&sc,  g_sc);

    cudaFuncSetAttribute(gemm_tf32mma, cudaFuncAttributeMaxDynamicSharedMemorySize, SMEM_BYTES);

    // 0) Wt[e][d] = W[d][e]
    transpose_f32<<<dim3(3 * DDIM / 32, DDIM / 32, 1), dim3(32, 8)>>>(
        W, 0LL, 3 * DDIM, wt, 0LL, DDIM);

    // 1) qkv = x @ Wt^T + b   (M=16384, N=3072, K=1024)
    gemm_tf32mma<<<dim3(3 * DDIM / TN, BDIM * SDIM / TM, 1), 256, SMEM_BYTES>>>(
        x,   DDIM, 0LL,
        wt,  DDIM, 0LL,
        qkv, 3 * DDIM, 0LL,
        DDIM, b);

    // 2) Vt[b][d][s] = V[b][s][d]
    transpose_f32<<<dim3(DDIM / 32, SDIM / 32, BDIM), dim3(32, 8)>>>(
        qkv + 2 * DDIM, (long long)SDIM * 3 * DDIM, 3 * DDIM,
        vt,             (long long)DDIM * SDIM,     SDIM);

    // 3) scores = Q @ K^T   (per batch: M=4096, N=4096, K=1024)
    gemm_tf32mma<<<dim3(SDIM / TN, SDIM / TM, BDIM), 256, SMEM_BYTES>>>(
        qkv,        3 * DDIM, (long long)SDIM * 3 * DDIM,
        qkv + DDIM, 3 * DDIM, (long long)SDIM * 3 * DDIM,
        sc,         SDIM,     (long long)SDIM * SDIM,
        DDIM, (const float*)0);

    // 4) softmax rows (scale = D^-0.5 = 1/32)
    softmax4096<<<BDIM * SDIM, 256>>>(sc, 0.03125f);

    // 5) out = P @ Vt^T   (per batch: M=4096, N=1024, K=4096)
    gemm_tf32mma<<<dim3(DDIM / TN, SDIM / TM, BDIM), 256, SMEM_BYTES>>>(
        sc,  SDIM, (long long)SDIM * SDIM,
        vt,  SDIM, (long long)DDIM * SDIM,
        out, DDIM, (long long)SDIM * DDIM,
        SDIM, (const float*)0);
}